// round 12
// baseline (speedup 1.0000x reference)
#include <cuda_runtime.h>
#include <cuda_bf16.h>
#include <cstdint>

#define N0_   500000
#define N1_   100000
#define N2_   25000
#define E0_   1600000
#define E1_   400000
#define D_IN_ 128
#define D_H_  256
#define D_OUT_ 128

#define PAD0_ 102400
#define TOT_  128000
#define SBLK_ 125

// ---- scratch (allocation-free rule: __device__ globals) ----
__device__ int g_deg[TOT_];
__device__ int g_scan[TOT_];
__device__ int g_bsum[SBLK_];
__device__ int g_bsum2[SBLK_];
__device__ int g_off[TOT_];
__device__ int g_wcur[TOT_];
__device__ int g_csr0[E0_];
__device__ int g_csr1[E1_];
// h stored as bf16 hi/lo pair (replaces fp32 h)
__device__ __align__(128) __nv_bfloat16 g_Hh[(size_t)N1_ * 256];
__device__ __align__(128) __nv_bfloat16 g_Hl[(size_t)N1_ * 256];
__device__ __align__(128) __nv_bfloat16 g_A1h[(size_t)N1_ * 256];
__device__ __align__(128) __nv_bfloat16 g_A1l[(size_t)N1_ * 256];
__device__ __align__(128) __nv_bfloat16 g_A2h[(size_t)N2_ * 256];
__device__ __align__(128) __nv_bfloat16 g_A2l[(size_t)N2_ * 256];
__device__ __align__(128) __nv_bfloat16 g_B1h[256 * 256];
__device__ __align__(128) __nv_bfloat16 g_B1l[256 * 256];
__device__ __align__(128) __nv_bfloat16 g_B2h[128 * 512];
__device__ __align__(128) __nv_bfloat16 g_B2l[128 * 512];

// ---------------- ptx helpers (compute_103-safe) ----------------
__device__ __forceinline__ uint32_t smem_u32(const void* p) {
    uint32_t a;
    asm("{ .reg .u64 t; cvta.to.shared.u64 t, %1; cvt.u32.u64 %0, t; }" : "=r"(a) : "l"(p));
    return a;
}
__device__ __forceinline__ uint32_t sw128(uint32_t off) {
    return off ^ ((off >> 3) & 0x70);
}
__device__ __forceinline__ void cp16(uint32_t dst, const void* src, bool pred) {
    int sz = pred ? 16 : 0;
    asm volatile("cp.async.cg.shared.global [%0], [%1], 16, %2;"
                 :: "r"(dst), "l"(src), "r"(sz) : "memory");
}
__device__ __forceinline__ void ldsm4(uint32_t& r0, uint32_t& r1, uint32_t& r2, uint32_t& r3,
                                      uint32_t addr) {
    asm volatile("ldmatrix.sync.aligned.m8n8.x4.shared.b16 {%0,%1,%2,%3}, [%4];"
                 : "=r"(r0), "=r"(r1), "=r"(r2), "=r"(r3) : "r"(addr));
}
__device__ __forceinline__ void mma16816(float* c, uint32_t a0, uint32_t a1, uint32_t a2,
                                         uint32_t a3, uint32_t b0, uint32_t b1) {
    asm volatile(
        "mma.sync.aligned.m16n8k16.row.col.f32.bf16.bf16.f32 "
        "{%0,%1,%2,%3}, {%4,%5,%6,%7}, {%8,%9}, {%0,%1,%2,%3};"
        : "+f"(c[0]), "+f"(c[1]), "+f"(c[2]), "+f"(c[3])
        : "r"(a0), "r"(a1), "r"(a2), "r"(a3), "r"(b0), "r"(b1));
}
__device__ __forceinline__ uint32_t pack_bf16x2(float a, float b) {
    __nv_bfloat162 p = __floats2bfloat162_rn(a, b);
    return *(uint32_t*)&p;
}
__device__ __forceinline__ float2 bf2_to_f2(uint32_t u) {
    __nv_bfloat162 b = *(__nv_bfloat162*)&u;
    return __bfloat1622float2(b);
}
__device__ __forceinline__ void split_store(__nv_bfloat16* hi, __nv_bfloat16* lo,
                                            size_t o, float4 v) {
    float hx = __bfloat162float(__float2bfloat16(v.x));
    float hy = __bfloat162float(__float2bfloat16(v.y));
    float hz = __bfloat162float(__float2bfloat16(v.z));
    float hw = __bfloat162float(__float2bfloat16(v.w));
    uint2 ph = make_uint2(pack_bf16x2(hx, hy), pack_bf16x2(hz, hw));
    uint2 pl = make_uint2(pack_bf16x2(v.x - hx, v.y - hy),
                          pack_bf16x2(v.z - hz, v.w - hw));
    *(uint2*)(hi + o) = ph;
    *(uint2*)(lo + o) = pl;
}

// ---------------- CSR build kernels ----------------
__global__ void zero_deg(int4* deg) {
    int i = blockIdx.x * blockDim.x + threadIdx.x;
    if (i < TOT_ / 4) deg[i] = make_int4(0, 0, 0, 0);
}

__global__ void hist_deg(const int* __restrict__ d0, const int* __restrict__ d1,
                         int* __restrict__ deg) {
    int i = blockIdx.x * blockDim.x + threadIdx.x;
    if (i < E0_) atomicAdd(&deg[d0[i]], 1);
    else if (i < E0_ + E1_) atomicAdd(&deg[PAD0_ + d1[i - E0_]], 1);
}

__global__ void __launch_bounds__(1024) scan_part(const int* __restrict__ deg,
                                                  int* __restrict__ scn,
                                                  int* __restrict__ bsum) {
    __shared__ int sm[1024];
    int t = threadIdx.x;
    int gid = blockIdx.x * 1024 + t;
    sm[t] = deg[gid];
    __syncthreads();
    #pragma unroll
    for (int o = 1; o < 1024; o <<= 1) {
        int u = (t >= o) ? sm[t - o] : 0;
        __syncthreads();
        sm[t] += u;
        __syncthreads();
    }
    scn[gid] = sm[t];
    if (t == 1023) bsum[blockIdx.x] = sm[t];
}

__global__ void __launch_bounds__(128) scan_top(const int* __restrict__ bsum,
                                                int* __restrict__ bsum2) {
    __shared__ int sm[128];
    int t = threadIdx.x;
    sm[t] = (t < SBLK_) ? bsum[t] : 0;
    __syncthreads();
    #pragma unroll
    for (int o = 1; o < 128; o <<= 1) {
        int u = (t >= o) ? sm[t - o] : 0;
        __syncthreads();
        sm[t] += u;
        __syncthreads();
    }
    if (t < SBLK_) bsum2[t] = sm[t];
}

__global__ void scan_add(const int* __restrict__ scn, const int* __restrict__ deg,
                         const int* __restrict__ bsum2,
                         int* __restrict__ off, int* __restrict__ wcur) {
    int gid = blockIdx.x * blockDim.x + threadIdx.x;
    if (gid >= TOT_) return;
    int b = gid >> 10;
    int incl = scn[gid] + (b > 0 ? bsum2[b - 1] : 0);
    int start = incl - deg[gid];
    if (gid >= PAD0_) start -= E0_;
    off[gid] = start;
    wcur[gid] = start;
}

__global__ void fill_csr(const int* __restrict__ s0, const int* __restrict__ d0,
                         const int* __restrict__ s1, const int* __restrict__ d1,
                         int* __restrict__ wcur,
                         int* __restrict__ csr0, int* __restrict__ csr1) {
    int i = blockIdx.x * blockDim.x + threadIdx.x;
    if (i < E0_) {
        int pos = atomicAdd(&wcur[d0[i]], 1);
        csr0[pos] = s0[i];
    } else if (i < E0_ + E1_) {
        int j = i - E0_;
        int pos = atomicAdd(&wcur[PAD0_ + d1[j]], 1);
        csr1[pos] = s1[j];
    }
}

// ---------------- atomic-free gather + mean + bf16 split ----------------
__global__ void __launch_bounds__(256) gather0(const float* __restrict__ x,
                                               const int* __restrict__ off,
                                               const int* __restrict__ csr,
                                               __nv_bfloat16* __restrict__ hi,
                                               __nv_bfloat16* __restrict__ lo) {
    int row = (blockIdx.x * blockDim.x + threadIdx.x) >> 5;
    int lane = threadIdx.x & 31;
    if (row >= N1_) return;
    int start = off[row];
    int deg = off[row + 1] - start;

    float4 acc = make_float4(0.f, 0.f, 0.f, 0.f);
    for (int base = 0; base < deg; base += 32) {
        int idx = 0;
        if (base + lane < deg) idx = __ldg(csr + start + base + lane);
        int nn = min(32, deg - base);
        #pragma unroll 4
        for (int j = 0; j < nn; j++) {
            int s = __shfl_sync(0xffffffffu, idx, j);
            float4 v = __ldg((const float4*)(x + (size_t)s * D_IN_) + lane);
            acc.x += v.x; acc.y += v.y; acc.z += v.z; acc.w += v.w;
        }
    }
    float inv = 1.0f / fmaxf((float)deg, 1.0f);
    acc.x *= inv; acc.y *= inv; acc.z *= inv; acc.w *= inv;
    size_t ro = (size_t)row * 256 + lane * 4;
    split_store(hi, lo, ro, acc);
    float4 xr = __ldg((const float4*)(x + (size_t)row * D_IN_) + lane);
    split_store(hi, lo, ro + 128, xr);
}

// hop 1 gather over bf16 hi/lo h: reads 512 B per neighbor (vs 1024 fp32).
// Writes A2 left half [N2, 256] hi/lo (stride 256).
__global__ void __launch_bounds__(256) gather1(const __nv_bfloat16* __restrict__ Hh,
                                               const __nv_bfloat16* __restrict__ Hl,
                                               const int* __restrict__ off,
                                               const int* __restrict__ csr,
                                               __nv_bfloat16* __restrict__ A2h,
                                               __nv_bfloat16* __restrict__ A2l) {
    int row = (blockIdx.x * blockDim.x + threadIdx.x) >> 5;
    int lane = threadIdx.x & 31;
    if (row >= N2_) return;
    int start = off[PAD0_ + row];
    int deg = off[PAD0_ + row + 1] - start;

    float a[8];
    #pragma unroll
    for (int k = 0; k < 8; k++) a[k] = 0.f;

    for (int base = 0; base < deg; base += 32) {
        int idx = 0;
        if (base + lane < deg) idx = __ldg(csr + start + base + lane);
        int nn = min(32, deg - base);
        #pragma unroll 4
        for (int j = 0; j < nn; j++) {
            int s = __shfl_sync(0xffffffffu, idx, j);
            uint4 vh = __ldg((const uint4*)(Hh + (size_t)s * 256) + lane);
            uint4 vl = __ldg((const uint4*)(Hl + (size_t)s * 256) + lane);
            float2 p;
            p = bf2_to_f2(vh.x); a[0] += p.x; a[1] += p.y;
            p = bf2_to_f2(vl.x); a[0] += p.x; a[1] += p.y;
            p = bf2_to_f2(vh.y); a[2] += p.x; a[3] += p.y;
            p = bf2_to_f2(vl.y); a[2] += p.x; a[3] += p.y;
            p = bf2_to_f2(vh.z); a[4] += p.x; a[5] += p.y;
            p = bf2_to_f2(vl.z); a[4] += p.x; a[5] += p.y;
            p = bf2_to_f2(vh.w); a[6] += p.x; a[7] += p.y;
            p = bf2_to_f2(vl.w); a[6] += p.x; a[7] += p.y;
        }
    }
    float inv = 1.0f / fmaxf((float)deg, 1.0f);
    #pragma unroll
    for (int k = 0; k < 8; k++) a[k] *= inv;
    size_t ro = (size_t)row * 256 + lane * 8;
    split_store(A2h, A2l, ro,     make_float4(a[0], a[1], a[2], a[3]));
    split_store(A2h, A2l, ro + 4, make_float4(a[4], a[5], a[6], a[7]));
}

// both weight matrices concat+split in ONE launch.
__global__ void split_weights(const float* __restrict__ Wl0, const float* __restrict__ Wr0,
                              const float* __restrict__ Wl1, const float* __restrict__ Wr1,
                              __nv_bfloat16* __restrict__ B1h, __nv_bfloat16* __restrict__ B1l,
                              __nv_bfloat16* __restrict__ B2h, __nv_bfloat16* __restrict__ B2l) {
    const int T1 = 256 * (256 / 4);
    const int T2 = 128 * (512 / 4);
    int i = blockIdx.x * blockDim.x + threadIdx.x;
    if (i < T1) {
        int row = i / 64;
        int c4 = (i % 64) * 4;
        float4 v = (c4 < 128) ? *(const float4*)(Wl0 + (size_t)row * 128 + c4)
                              : *(const float4*)(Wr0 + (size_t)row * 128 + (c4 - 128));
        split_store(B1h, B1l, (size_t)row * 256 + c4, v);
    } else if (i < T1 + T2) {
        int k = i - T1;
        int row = k / 128;
        int c4 = (k % 128) * 4;
        float4 v = (c4 < 256) ? *(const float4*)(Wl1 + (size_t)row * 256 + c4)
                              : *(const float4*)(Wr1 + (size_t)row * 256 + (c4 - 256));
        split_store(B2h, B2l, (size_t)row * 512 + c4, v);
    }
}

// ---------------- mma.sync bf16 GEMM: 128x128 tiles, 2 CTAs/SM ----------------
// A is dual-source along K: cols [0,K0) from {A0h,A0l} (stride K0),
// cols [K0,K) from {A1h,A1l} (stride K-K0). 3 split passes as before.
// SPLITOUT: epilogue writes bf16 hi/lo (Hh/Hl, stride Nstride) instead of fp32 C.
template<int K, int K0, bool RELU, bool SPLITOUT>
__global__ void __launch_bounds__(256, 2)
gemm_mma(const __nv_bfloat16* __restrict__ A0h, const __nv_bfloat16* __restrict__ A0l,
         const __nv_bfloat16* __restrict__ A1h, const __nv_bfloat16* __restrict__ A1l,
         const __nv_bfloat16* __restrict__ Bh, const __nv_bfloat16* __restrict__ Bl,
         const float* __restrict__ bias, float* __restrict__ C,
         __nv_bfloat16* __restrict__ Hh, __nv_bfloat16* __restrict__ Hl,
         int M, int Nstride) {
    constexpr int STAGES = 3;
    constexpr int KC = 64;
    constexpr int NCP = K / KC;
    constexpr int NCHUNK = 3 * NCP;
    constexpr int ATILE = 128 * 128;
    constexpr int STILE = 2 * ATILE;
    constexpr int MT = 4;
    constexpr int NT = 4;
    constexpr int NG = 2048 / 256;

    extern __shared__ char dsm[];
    char* tb = (char*)((((uintptr_t)dsm) + 1023) & ~(uintptr_t)1023);
    uint32_t aBase[STAGES], bBase[STAGES];
    #pragma unroll
    for (int s = 0; s < STAGES; s++) {
        aBase[s] = smem_u32(tb + s * STILE);
        bBase[s] = smem_u32(tb + s * STILE + ATILE);
    }

    const int tid  = threadIdx.x;
    const int wid  = tid >> 5;
    const int lane = tid & 31;
    const int bn0  = blockIdx.x * 128;
    const int m0   = blockIdx.y * 128;
    const int wm0  = (wid >> 2) * 64;
    const int wn0  = (wid & 3) * 32;

    float acc[MT][NT][4];
    #pragma unroll
    for (int i = 0; i < MT; i++)
        #pragma unroll
        for (int j = 0; j < NT; j++)
            #pragma unroll
            for (int e = 0; e < 4; e++) acc[i][j][e] = 0.f;

    auto load_chunk = [&](int ch, int buf) {
        const int pass = ch / NCP;
        const int kc = (ch % NCP) * KC;
        const __nv_bfloat16* A0 = (pass < 2) ? A0h : A0l;
        const __nv_bfloat16* A1 = (pass < 2) ? A1h : A1l;
        const __nv_bfloat16* Bs = (pass == 1) ? Bl : Bh;
        #pragma unroll
        for (int it = 0; it < NG; it++) {
            int g = tid + it * 256;
            if (g < 1024) {
                int row = g >> 3, c = g & 7;
                int gr = m0 + row;
                bool ok = gr < M;
                int grs = ok ? gr : (M - 1);
                int kcol = kc + c * 8;
                const __nv_bfloat16* src =
                    (K0 == K || kcol < K0)
                        ? A0 + (size_t)grs * K0 + kcol
                        : A1 + (size_t)grs * (K - K0) + (kcol - K0);
                cp16(aBase[buf] + sw128((uint32_t)(row * 128 + c * 16)), src, ok);
            } else {
                int g2 = g - 1024;
                int row = g2 >> 3, c = g2 & 7;
                cp16(bBase[buf] + sw128((uint32_t)(row * 128 + c * 16)),
                     Bs + (size_t)(bn0 + row) * K + kc + c * 8, true);
            }
        }
        asm volatile("cp.async.commit_group;" ::: "memory");
    };

    #pragma unroll
    for (int s = 0; s < STAGES - 1; s++) load_chunk(s, s);

    for (int ch = 0; ch < NCHUNK; ch++) {
        const int buf = ch % STAGES;
        if (ch == NCHUNK - 1)
            asm volatile("cp.async.wait_group 0;" ::: "memory");
        else
            asm volatile("cp.async.wait_group %0;" :: "n"(STAGES - 2) : "memory");
        __syncthreads();
        int nx = ch + STAGES - 1;
        if (nx < NCHUNK) load_chunk(nx, nx % STAGES);

        const uint32_t aB = aBase[buf];
        const uint32_t bB = bBase[buf];
        #pragma unroll
        for (int ks = 0; ks < 4; ks++) {
            const int kb = ks * 32;
            uint32_t bf[NT][2];
            #pragma unroll
            for (int nt2 = 0; nt2 < NT / 2; nt2++) {
                int n0 = wn0 + nt2 * 16;
                int rsel = (lane & 7) + ((lane >> 4) << 3);
                int ksel = (lane >> 3) & 1;
                uint32_t off = (uint32_t)((n0 + rsel) * 128 + kb + ksel * 16);
                ldsm4(bf[2 * nt2][0], bf[2 * nt2][1],
                      bf[2 * nt2 + 1][0], bf[2 * nt2 + 1][1], bB + sw128(off));
            }
            #pragma unroll
            for (int mt = 0; mt < MT; mt++) {
                int mrow = wm0 + mt * 16;
                int rsel = (lane & 7) + (((lane >> 3) & 1) << 3);
                int ksel = lane >> 4;
                uint32_t off = (uint32_t)((mrow + rsel) * 128 + kb + ksel * 16);
                uint32_t a0, a1, a2, a3;
                ldsm4(a0, a1, a2, a3, aB + sw128(off));
                #pragma unroll
                for (int nt = 0; nt < NT; nt++)
                    mma16816(acc[mt][nt], a0, a1, a2, a3, bf[nt][0], bf[nt][1]);
            }
        }
    }

    // epilogue
    #pragma unroll
    for (int mt = 0; mt < MT; mt++) {
        int rr[2];
        rr[0] = m0 + wm0 + mt * 16 + (lane >> 2);
        rr[1] = rr[0] + 8;
        #pragma unroll
        for (int nt = 0; nt < NT; nt++) {
            int c = bn0 + wn0 + nt * 8 + (lane & 3) * 2;
            float2 bv = *(const float2*)(bias + c);
            #pragma unroll
            for (int half = 0; half < 2; half++) {
                int r = rr[half];
                if (r < M) {
                    float2 v = make_float2(acc[mt][nt][2 * half + 0] + bv.x,
                                           acc[mt][nt][2 * half + 1] + bv.y);
                    if (RELU) { v.x = fmaxf(v.x, 0.f); v.y = fmaxf(v.y, 0.f); }
                    if (SPLITOUT) {
                        float hx = __bfloat162float(__float2bfloat16(v.x));
                        float hy = __bfloat162float(__float2bfloat16(v.y));
                        size_t o = (size_t)r * Nstride + c;
                        *(uint32_t*)(Hh + o) = pack_bf16x2(hx, hy);
                        *(uint32_t*)(Hl + o) = pack_bf16x2(v.x - hx, v.y - hy);
                    } else {
                        *(float2*)(C + (size_t)r * Nstride + c) = v;
                    }
                }
            }
        }
    }
}

// ---------------- host side ----------------
extern "C" void kernel_launch(void* const* d_in, const int* in_sizes, int n_in,
                              void* d_out, int out_size) {
    const float* x   = (const float*)d_in[0];
    const float* Wl0 = (const float*)d_in[1];
    const float* bl0 = (const float*)d_in[2];
    const float* Wr0 = (const float*)d_in[3];
    const float* Wl1 = (const float*)d_in[4];
    const float* bl1 = (const float*)d_in[5];
    const float* Wr1 = (const float*)d_in[6];
    const int* e0s = (const int*)d_in[7];
    const int* e0d = (const int*)d_in[8];
    const int* e1s = (const int*)d_in[9];
    const int* e1d = (const int*)d_in[10];
    float* out = (float*)d_out;

    int *deg, *scn, *bsum, *bsum2, *off, *wcur, *csr0, *csr1;
    __nv_bfloat16 *Hh, *Hl, *A1h, *A1l, *A2h, *A2l, *B1h, *B1l, *B2h, *B2l;
    cudaGetSymbolAddress((void**)&deg,  g_deg);
    cudaGetSymbolAddress((void**)&scn,  g_scan);
    cudaGetSymbolAddress((void**)&bsum, g_bsum);
    cudaGetSymbolAddress((void**)&bsum2, g_bsum2);
    cudaGetSymbolAddress((void**)&off,  g_off);
    cudaGetSymbolAddress((void**)&wcur, g_wcur);
    cudaGetSymbolAddress((void**)&csr0, g_csr0);
    cudaGetSymbolAddress((void**)&csr1, g_csr1);
    cudaGetSymbolAddress((void**)&Hh,  g_Hh);
    cudaGetSymbolAddress((void**)&Hl,  g_Hl);
    cudaGetSymbolAddress((void**)&A1h, g_A1h);
    cudaGetSymbolAddress((void**)&A1l, g_A1l);
    cudaGetSymbolAddress((void**)&A2h, g_A2h);
    cudaGetSymbolAddress((void**)&A2l, g_A2l);
    cudaGetSymbolAddress((void**)&B1h, g_B1h);
    cudaGetSymbolAddress((void**)&B1l, g_B1l);
    cudaGetSymbolAddress((void**)&B2h, g_B2h);
    cudaGetSymbolAddress((void**)&B2l, g_B2l);

    const int smemg = 1024 + 3 * (128 * 128 + 128 * 128);  // 99328 per CTA
    cudaFuncSetAttribute(gemm_mma<256, 256, true, true>,
                         cudaFuncAttributeMaxDynamicSharedMemorySize, smemg);
    cudaFuncSetAttribute(gemm_mma<512, 256, false, false>,
                         cudaFuncAttributeMaxDynamicSharedMemorySize, smemg);

    const int ET = E0_ + E1_;

    // CSR build
    zero_deg<<<(TOT_ / 4 + 255) / 256, 256>>>((int4*)deg);
    hist_deg<<<(ET + 255) / 256, 256>>>(e0d, e1d, deg);
    scan_part<<<SBLK_, 1024>>>(deg, scn, bsum);
    scan_top<<<1, 128>>>(bsum, bsum2);
    scan_add<<<(TOT_ + 255) / 256, 256>>>(scn, deg, bsum2, off, wcur);
    fill_csr<<<(ET + 255) / 256, 256>>>(e0s, e0d, e1s, e1d, wcur, csr0, csr1);

    // weight splits (single launch)
    {
        int tot = 256 * 64 + 128 * 128;
        split_weights<<<(tot + 255) / 256, 256>>>(Wl0, Wr0, Wl1, Wr1,
                                                  B1h, B1l, B2h, B2l);
    }

    // hop 0: gather + mean + split -> A1 (both halves)
    gather0<<<(N1_ * 32 + 255) / 256, 256>>>(x, off, csr0, A1h, A1l);

    // gemm1: h = relu(A1 @ B1^T + bl0), written directly as bf16 hi/lo (Hh, Hl)
    {
        dim3 grid(2, (N1_ + 127) / 128);
        gemm_mma<256, 256, true, true><<<grid, 256, smemg>>>(
            A1h, A1l, A1h, A1l, B1h, B1l, bl0,
            (float*)nullptr, Hh, Hl, N1_, 256);
    }

    // hop 1: gather over bf16 h -> A2 left half [N2, 256]
    gather1<<<(N2_ * 32 + 255) / 256, 256>>>(Hh, Hl, off, csr1, A2h, A2l);

    // gemm2: out = [A2 | h[:N2]] @ B2^T + bl1 (A right half read from Hh/Hl)
    {
        dim3 grid(1, (N2_ + 127) / 128);
        gemm_mma<512, 256, false, false><<<grid, 256, smemg>>>(
            A2h, A2l, Hh, Hl, B2h, B2l, bl1,
            out, (__nv_bfloat16*)nullptr, (__nv_bfloat16*)nullptr, N2_, 128);
    }
}

// round 13
// speedup vs baseline: 1.0397x; 1.0397x over previous
#include <cuda_runtime.h>
#include <cuda_bf16.h>
#include <cstdint>

#define N0_   500000
#define N1_   100000
#define N2_   25000
#define E0_   1600000
#define E1_   400000
#define D_IN_ 128
#define D_H_  256
#define D_OUT_ 128

#define PAD0_ 102400
#define TOT_  128000
#define SBLK_ 125

// ---- scratch (allocation-free rule: __device__ globals) ----
__device__ float g_h[(size_t)N1_ * D_H_];
__device__ int g_deg[TOT_];
__device__ int g_scan[TOT_];
__device__ int g_bsum[SBLK_];
__device__ int g_bsum2[SBLK_];
__device__ int g_off[TOT_];
__device__ int g_wcur[TOT_];
__device__ int g_csr0[E0_];
__device__ int g_csr1[E1_];
__device__ __align__(128) __nv_bfloat16 g_A1h[(size_t)N1_ * 256];
__device__ __align__(128) __nv_bfloat16 g_A1l[(size_t)N1_ * 256];
__device__ __align__(128) __nv_bfloat16 g_A2h[(size_t)N2_ * 512];
__device__ __align__(128) __nv_bfloat16 g_A2l[(size_t)N2_ * 512];
__device__ __align__(128) __nv_bfloat16 g_B1h[256 * 256];
__device__ __align__(128) __nv_bfloat16 g_B1l[256 * 256];
__device__ __align__(128) __nv_bfloat16 g_B2h[128 * 512];
__device__ __align__(128) __nv_bfloat16 g_B2l[128 * 512];

// ---------------- ptx helpers (compute_103-safe) ----------------
__device__ __forceinline__ uint32_t smem_u32(const void* p) {
    uint32_t a;
    asm("{ .reg .u64 t; cvta.to.shared.u64 t, %1; cvt.u32.u64 %0, t; }" : "=r"(a) : "l"(p));
    return a;
}
__device__ __forceinline__ uint32_t sw128(uint32_t off) {
    return off ^ ((off >> 3) & 0x70);
}
__device__ __forceinline__ void cp16(uint32_t dst, const void* src, bool pred) {
    int sz = pred ? 16 : 0;
    asm volatile("cp.async.cg.shared.global [%0], [%1], 16, %2;"
                 :: "r"(dst), "l"(src), "r"(sz) : "memory");
}
__device__ __forceinline__ void ldsm4(uint32_t& r0, uint32_t& r1, uint32_t& r2, uint32_t& r3,
                                      uint32_t addr) {
    asm volatile("ldmatrix.sync.aligned.m8n8.x4.shared.b16 {%0,%1,%2,%3}, [%4];"
                 : "=r"(r0), "=r"(r1), "=r"(r2), "=r"(r3) : "r"(addr));
}
__device__ __forceinline__ void mma16816(float* c, uint32_t a0, uint32_t a1, uint32_t a2,
                                         uint32_t a3, uint32_t b0, uint32_t b1) {
    asm volatile(
        "mma.sync.aligned.m16n8k16.row.col.f32.bf16.bf16.f32 "
        "{%0,%1,%2,%3}, {%4,%5,%6,%7}, {%8,%9}, {%0,%1,%2,%3};"
        : "+f"(c[0]), "+f"(c[1]), "+f"(c[2]), "+f"(c[3])
        : "r"(a0), "r"(a1), "r"(a2), "r"(a3), "r"(b0), "r"(b1));
}
__device__ __forceinline__ uint32_t pack_bf16x2(float a, float b) {
    __nv_bfloat162 p = __floats2bfloat162_rn(a, b);
    return *(uint32_t*)&p;
}
__device__ __forceinline__ void split_store(__nv_bfloat16* hi, __nv_bfloat16* lo,
                                            size_t o, float4 v) {
    float hx = __bfloat162float(__float2bfloat16(v.x));
    float hy = __bfloat162float(__float2bfloat16(v.y));
    float hz = __bfloat162float(__float2bfloat16(v.z));
    float hw = __bfloat162float(__float2bfloat16(v.w));
    uint2 ph = make_uint2(pack_bf16x2(hx, hy), pack_bf16x2(hz, hw));
    uint2 pl = make_uint2(pack_bf16x2(v.x - hx, v.y - hy),
                          pack_bf16x2(v.z - hz, v.w - hw));
    *(uint2*)(hi + o) = ph;
    *(uint2*)(lo + o) = pl;
}

// ---------------- prep: zero degree array + split both weight matrices ----------------
__global__ void prep_kernel(int4* deg,
                            const float* __restrict__ Wl0, const float* __restrict__ Wr0,
                            const float* __restrict__ Wl1, const float* __restrict__ Wr1,
                            __nv_bfloat16* __restrict__ B1h, __nv_bfloat16* __restrict__ B1l,
                            __nv_bfloat16* __restrict__ B2h, __nv_bfloat16* __restrict__ B2l) {
    const int Z = TOT_ / 4;                  // 32000
    const int T1 = 256 * (256 / 4);          // 16384
    const int T2 = 128 * (512 / 4);          // 16384
    int i = blockIdx.x * blockDim.x + threadIdx.x;
    if (i < Z) {
        deg[i] = make_int4(0, 0, 0, 0);
    } else if (i < Z + T1) {
        int k = i - Z;
        int row = k / 64;
        int c4 = (k % 64) * 4;
        float4 v = (c4 < 128) ? *(const float4*)(Wl0 + (size_t)row * 128 + c4)
                              : *(const float4*)(Wr0 + (size_t)row * 128 + (c4 - 128));
        split_store(B1h, B1l, (size_t)row * 256 + c4, v);
    } else if (i < Z + T1 + T2) {
        int k = i - Z - T1;
        int row = k / 128;
        int c4 = (k % 128) * 4;
        float4 v = (c4 < 256) ? *(const float4*)(Wl1 + (size_t)row * 256 + c4)
                              : *(const float4*)(Wr1 + (size_t)row * 256 + (c4 - 256));
        split_store(B2h, B2l, (size_t)row * 512 + c4, v);
    }
}

// ---------------- CSR build kernels ----------------
__global__ void hist_deg(const int* __restrict__ d0, const int* __restrict__ d1,
                         int* __restrict__ deg) {
    int i = blockIdx.x * blockDim.x + threadIdx.x;
    if (i < E0_) atomicAdd(&deg[d0[i]], 1);
    else if (i < E0_ + E1_) atomicAdd(&deg[PAD0_ + d1[i - E0_]], 1);
}

__global__ void __launch_bounds__(1024) scan_part(const int* __restrict__ deg,
                                                  int* __restrict__ scn,
                                                  int* __restrict__ bsum) {
    __shared__ int sm[1024];
    int t = threadIdx.x;
    int gid = blockIdx.x * 1024 + t;
    sm[t] = deg[gid];
    __syncthreads();
    #pragma unroll
    for (int o = 1; o < 1024; o <<= 1) {
        int u = (t >= o) ? sm[t - o] : 0;
        __syncthreads();
        sm[t] += u;
        __syncthreads();
    }
    scn[gid] = sm[t];
    if (t == 1023) bsum[blockIdx.x] = sm[t];
}

__global__ void __launch_bounds__(128) scan_top(const int* __restrict__ bsum,
                                                int* __restrict__ bsum2) {
    __shared__ int sm[128];
    int t = threadIdx.x;
    sm[t] = (t < SBLK_) ? bsum[t] : 0;
    __syncthreads();
    #pragma unroll
    for (int o = 1; o < 128; o <<= 1) {
        int u = (t >= o) ? sm[t - o] : 0;
        __syncthreads();
        sm[t] += u;
        __syncthreads();
    }
    if (t < SBLK_) bsum2[t] = sm[t];
}

__global__ void scan_add(const int* __restrict__ scn, const int* __restrict__ deg,
                         const int* __restrict__ bsum2,
                         int* __restrict__ off, int* __restrict__ wcur) {
    int gid = blockIdx.x * blockDim.x + threadIdx.x;
    if (gid >= TOT_) return;
    int b = gid >> 10;
    int incl = scn[gid] + (b > 0 ? bsum2[b - 1] : 0);
    int start = incl - deg[gid];
    if (gid >= PAD0_) start -= E0_;
    off[gid] = start;
    wcur[gid] = start;
}

__global__ void fill_csr(const int* __restrict__ s0, const int* __restrict__ d0,
                         const int* __restrict__ s1, const int* __restrict__ d1,
                         int* __restrict__ wcur,
                         int* __restrict__ csr0, int* __restrict__ csr1) {
    int i = blockIdx.x * blockDim.x + threadIdx.x;
    if (i < E0_) {
        int pos = atomicAdd(&wcur[d0[i]], 1);
        csr0[pos] = s0[i];
    } else if (i < E0_ + E1_) {
        int j = i - E0_;
        int pos = atomicAdd(&wcur[PAD0_ + d1[j]], 1);
        csr1[pos] = s1[j];
    }
}

// ---------------- atomic-free gather + mean + bf16 split ----------------
__global__ void __launch_bounds__(256) gather0(const float* __restrict__ x,
                                               const int* __restrict__ off,
                                               const int* __restrict__ csr,
                                               __nv_bfloat16* __restrict__ hi,
                                               __nv_bfloat16* __restrict__ lo) {
    int row = (blockIdx.x * blockDim.x + threadIdx.x) >> 5;
    int lane = threadIdx.x & 31;
    if (row >= N1_) return;
    int start = off[row];
    int deg = off[row + 1] - start;

    float4 acc = make_float4(0.f, 0.f, 0.f, 0.f);
    for (int base = 0; base < deg; base += 32) {
        int idx = 0;
        if (base + lane < deg) idx = __ldg(csr + start + base + lane);
        int nn = min(32, deg - base);
        #pragma unroll 4
        for (int j = 0; j < nn; j++) {
            int s = __shfl_sync(0xffffffffu, idx, j);
            float4 v = __ldg((const float4*)(x + (size_t)s * D_IN_) + lane);
            acc.x += v.x; acc.y += v.y; acc.z += v.z; acc.w += v.w;
        }
    }
    float inv = 1.0f / fmaxf((float)deg, 1.0f);
    acc.x *= inv; acc.y *= inv; acc.z *= inv; acc.w *= inv;
    size_t ro = (size_t)row * 256 + lane * 4;
    split_store(hi, lo, ro, acc);
    float4 xr = __ldg((const float4*)(x + (size_t)row * D_IN_) + lane);
    split_store(hi, lo, ro + 128, xr);
}

__global__ void __launch_bounds__(256) gather1(const float* __restrict__ h,
                                               const int* __restrict__ off,
                                               const int* __restrict__ csr,
                                               __nv_bfloat16* __restrict__ hi,
                                               __nv_bfloat16* __restrict__ lo) {
    int row = (blockIdx.x * blockDim.x + threadIdx.x) >> 5;
    int lane = threadIdx.x & 31;
    if (row >= N2_) return;
    int start = off[PAD0_ + row];
    int deg = off[PAD0_ + row + 1] - start;

    float4 a0 = make_float4(0.f, 0.f, 0.f, 0.f);
    float4 a1 = make_float4(0.f, 0.f, 0.f, 0.f);
    for (int base = 0; base < deg; base += 32) {
        int idx = 0;
        if (base + lane < deg) idx = __ldg(csr + start + base + lane);
        int nn = min(32, deg - base);
        #pragma unroll 2
        for (int j = 0; j < nn; j++) {
            int s = __shfl_sync(0xffffffffu, idx, j);
            const float4* hr = (const float4*)(h + (size_t)s * D_H_);
            float4 v0 = __ldg(hr + lane);
            float4 v1 = __ldg(hr + 32 + lane);
            a0.x += v0.x; a0.y += v0.y; a0.z += v0.z; a0.w += v0.w;
            a1.x += v1.x; a1.y += v1.y; a1.z += v1.z; a1.w += v1.w;
        }
    }
    float inv = 1.0f / fmaxf((float)deg, 1.0f);
    a0.x *= inv; a0.y *= inv; a0.z *= inv; a0.w *= inv;
    a1.x *= inv; a1.y *= inv; a1.z *= inv; a1.w *= inv;
    size_t ro = (size_t)row * 512 + lane * 4;
    split_store(hi, lo, ro, a0);
    split_store(hi, lo, ro + 128, a1);
}

// ---------------- mma.sync bf16 GEMM: MTILE x 128 tiles, 2 CTAs/SM ----------------
// grid = (N/128, ceil(M/MTILE)). 8 warps as 2(M) x 4(N); warp tile (MTILE/2) x 32.
template<int K, int MTILE, bool RELU, bool WSPLIT>
__global__ void __launch_bounds__(256, 2)
gemm_mma(const __nv_bfloat16* __restrict__ Ah, const __nv_bfloat16* __restrict__ Al,
         const __nv_bfloat16* __restrict__ Bh, const __nv_bfloat16* __restrict__ Bl,
         const float* __restrict__ bias, float* __restrict__ C, int M, int Nstride,
         __nv_bfloat16* __restrict__ A2h, __nv_bfloat16* __restrict__ A2l, int n2) {
    constexpr int STAGES = 3;
    constexpr int KC = 64;
    constexpr int NCP = K / KC;
    constexpr int NCHUNK = 3 * NCP;
    constexpr int ATILE = MTILE * 128;
    constexpr int BTILE = 128 * 128;
    constexpr int STILE = ATILE + BTILE;
    constexpr int MT = MTILE / 32;           // m16 tiles per warp
    constexpr int NT = 4;                    // n8 tiles per warp (warp N = 32)
    constexpr int AG = MTILE * 8;            // A cp granules
    constexpr int NG = (AG + 1024) / 256;

    extern __shared__ char dsm[];
    char* tb = (char*)((((uintptr_t)dsm) + 1023) & ~(uintptr_t)1023);
    uint32_t aBase[STAGES], bBase[STAGES];
    #pragma unroll
    for (int s = 0; s < STAGES; s++) {
        aBase[s] = smem_u32(tb + s * STILE);
        bBase[s] = smem_u32(tb + s * STILE + ATILE);
    }

    const int tid  = threadIdx.x;
    const int wid  = tid >> 5;
    const int lane = tid & 31;
    const int bn0  = blockIdx.x * 128;
    const int m0   = blockIdx.y * MTILE;
    const int wm0  = (wid >> 2) * (MTILE / 2);
    const int wn0  = (wid & 3) * 32;

    float acc[MT][NT][4];
    #pragma unroll
    for (int i = 0; i < MT; i++)
        #pragma unroll
        for (int j = 0; j < NT; j++)
            #pragma unroll
            for (int e = 0; e < 4; e++) acc[i][j][e] = 0.f;

    auto load_chunk = [&](int ch, int buf) {
        const int pass = ch / NCP;
        const int kc = (ch % NCP) * KC;
        const __nv_bfloat16* As = (pass < 2) ? Ah : Al;
        const __nv_bfloat16* Bs = (pass == 1) ? Bl : Bh;
        #pragma unroll
        for (int it = 0; it < NG; it++) {
            int g = tid + it * 256;
            if (g < AG) {
                int row = g >> 3, c = g & 7;
                int gr = m0 + row;
                bool ok = gr < M;
                int grs = ok ? gr : (M - 1);
                cp16(aBase[buf] + sw128((uint32_t)(row * 128 + c * 16)),
                     As + (size_t)grs * K + kc + c * 8, ok);
            } else {
                int g2 = g - AG;
                int row = g2 >> 3, c = g2 & 7;
                cp16(bBase[buf] + sw128((uint32_t)(row * 128 + c * 16)),
                     Bs + (size_t)(bn0 + row) * K + kc + c * 8, true);
            }
        }
        asm volatile("cp.async.commit_group;" ::: "memory");
    };

    #pragma unroll
    for (int s = 0; s < STAGES - 1; s++) load_chunk(s, s);

    for (int ch = 0; ch < NCHUNK; ch++) {
        const int buf = ch % STAGES;
        if (ch == NCHUNK - 1)
            asm volatile("cp.async.wait_group 0;" ::: "memory");
        else
            asm volatile("cp.async.wait_group %0;" :: "n"(STAGES - 2) : "memory");
        __syncthreads();
        int nx = ch + STAGES - 1;
        if (nx < NCHUNK) load_chunk(nx, nx % STAGES);

        const uint32_t aB = aBase[buf];
        const uint32_t bB = bBase[buf];
        #pragma unroll
        for (int ks = 0; ks < 4; ks++) {
            const int kb = ks * 32;
            uint32_t bf[NT][2];
            #pragma unroll
            for (int nt2 = 0; nt2 < NT / 2; nt2++) {
                int n0 = wn0 + nt2 * 16;
                int rsel = (lane & 7) + ((lane >> 4) << 3);
                int ksel = (lane >> 3) & 1;
                uint32_t off = (uint32_t)((n0 + rsel) * 128 + kb + ksel * 16);
                ldsm4(bf[2 * nt2][0], bf[2 * nt2][1],
                      bf[2 * nt2 + 1][0], bf[2 * nt2 + 1][1], bB + sw128(off));
            }
            #pragma unroll
            for (int mt = 0; mt < MT; mt++) {
                int mrow = wm0 + mt * 16;
                int rsel = (lane & 7) + (((lane >> 3) & 1) << 3);
                int ksel = lane >> 4;
                uint32_t off = (uint32_t)((mrow + rsel) * 128 + kb + ksel * 16);
                uint32_t a0, a1, a2, a3;
                ldsm4(a0, a1, a2, a3, aB + sw128(off));
                #pragma unroll
                for (int nt = 0; nt < NT; nt++)
                    mma16816(acc[mt][nt], a0, a1, a2, a3, bf[nt][0], bf[nt][1]);
            }
        }
    }

    // epilogue
    #pragma unroll
    for (int mt = 0; mt < MT; mt++) {
        int rr[2];
        rr[0] = m0 + wm0 + mt * 16 + (lane >> 2);
        rr[1] = rr[0] + 8;
        #pragma unroll
        for (int nt = 0; nt < NT; nt++) {
            int c = bn0 + wn0 + nt * 8 + (lane & 3) * 2;
            float2 bv = *(const float2*)(bias + c);
            #pragma unroll
            for (int half = 0; half < 2; half++) {
                int r = rr[half];
                if (r < M) {
                    float2 v = make_float2(acc[mt][nt][2 * half + 0] + bv.x,
                                           acc[mt][nt][2 * half + 1] + bv.y);
                    if (RELU) { v.x = fmaxf(v.x, 0.f); v.y = fmaxf(v.y, 0.f); }
                    *(float2*)(C + (size_t)r * Nstride + c) = v;
                    if (WSPLIT && r < n2) {
                        float hx = __bfloat162float(__float2bfloat16(v.x));
                        float hy = __bfloat162float(__float2bfloat16(v.y));
                        size_t o = (size_t)r * 512 + 256 + c;
                        *(uint32_t*)(A2h + o) = pack_bf16x2(hx, hy);
                        *(uint32_t*)(A2l + o) = pack_bf16x2(v.x - hx, v.y - hy);
                    }
                }
            }
        }
    }
}

// ---------------- host side ----------------
extern "C" void kernel_launch(void* const* d_in, const int* in_sizes, int n_in,
                              void* d_out, int out_size) {
    const float* x   = (const float*)d_in[0];
    const float* Wl0 = (const float*)d_in[1];
    const float* bl0 = (const float*)d_in[2];
    const float* Wr0 = (const float*)d_in[3];
    const float* Wl1 = (const float*)d_in[4];
    const float* bl1 = (const float*)d_in[5];
    const float* Wr1 = (const float*)d_in[6];
    const int* e0s = (const int*)d_in[7];
    const int* e0d = (const int*)d_in[8];
    const int* e1s = (const int*)d_in[9];
    const int* e1d = (const int*)d_in[10];
    float* out = (float*)d_out;

    float* h;
    int *deg, *scn, *bsum, *bsum2, *off, *wcur, *csr0, *csr1;
    __nv_bfloat16 *A1h, *A1l, *A2h, *A2l, *B1h, *B1l, *B2h, *B2l;
    cudaGetSymbolAddress((void**)&h,    g_h);
    cudaGetSymbolAddress((void**)&deg,  g_deg);
    cudaGetSymbolAddress((void**)&scn,  g_scan);
    cudaGetSymbolAddress((void**)&bsum, g_bsum);
    cudaGetSymbolAddress((void**)&bsum2, g_bsum2);
    cudaGetSymbolAddress((void**)&off,  g_off);
    cudaGetSymbolAddress((void**)&wcur, g_wcur);
    cudaGetSymbolAddress((void**)&csr0, g_csr0);
    cudaGetSymbolAddress((void**)&csr1, g_csr1);
    cudaGetSymbolAddress((void**)&A1h, g_A1h);
    cudaGetSymbolAddress((void**)&A1l, g_A1l);
    cudaGetSymbolAddress((void**)&A2h, g_A2h);
    cudaGetSymbolAddress((void**)&A2l, g_A2l);
    cudaGetSymbolAddress((void**)&B1h, g_B1h);
    cudaGetSymbolAddress((void**)&B1l, g_B1l);
    cudaGetSymbolAddress((void**)&B2h, g_B2h);
    cudaGetSymbolAddress((void**)&B2l, g_B2l);

    const int smem1 = 1024 + 3 * (128 * 128 + 128 * 128);  // 99328
    const int smem2 = 1024 + 3 * (64 * 128 + 128 * 128);   // 74752
    cudaFuncSetAttribute(gemm_mma<256, 128, true, true>,
                         cudaFuncAttributeMaxDynamicSharedMemorySize, smem1);
    cudaFuncSetAttribute(gemm_mma<512, 64, false, false>,
                         cudaFuncAttributeMaxDynamicSharedMemorySize, smem2);

    const int ET = E0_ + E1_;

    // prep: zero deg + weight splits (one launch)
    {
        int tot = TOT_ / 4 + 256 * 64 + 128 * 128;  // 64768
        prep_kernel<<<(tot + 255) / 256, 256>>>((int4*)deg, Wl0, Wr0, Wl1, Wr1,
                                                B1h, B1l, B2h, B2l);
    }
    // CSR build
    hist_deg<<<(ET + 255) / 256, 256>>>(e0d, e1d, deg);
    scan_part<<<SBLK_, 1024>>>(deg, scn, bsum);
    scan_top<<<1, 128>>>(bsum, bsum2);
    scan_add<<<(TOT_ + 255) / 256, 256>>>(scn, deg, bsum2, off, wcur);
    fill_csr<<<(ET + 255) / 256, 256>>>(e0s, e0d, e1s, e1d, wcur, csr0, csr1);

    // hop 0: gather + mean + split -> A1 (both halves)
    gather0<<<(N1_ * 32 + 255) / 256, 256>>>(x, off, csr0, A1h, A1l);

    // h = relu(A1 @ B1^T + bl0); epilogue emits A2 right half (h[:N2])
    {
        dim3 grid(2, (N1_ + 127) / 128);
        gemm_mma<256, 128, true, true><<<grid, 256, smem1>>>(
            A1h, A1l, B1h, B1l, bl0, h, N1_, 256, A2h, A2l, N2_);
    }

    // hop 1: gather + mean + split -> A2 left half
    gather1<<<(N2_ * 32 + 255) / 256, 256>>>(h, off, csr1, A2h, A2l);

    // out = A2 @ B2^T + bl1 (MTILE=64 -> 391 CTAs, shorter tail)
    {
        dim3 grid(1, (N2_ + 63) / 64);
        gemm_mma<512, 64, false, false><<<grid, 256, smem2>>>(
            A2h, A2l, B2h, B2l, bl1, out, N2_, 128, (__nv_bfloat16*)nullptr,
            (__nv_bfloat16*)nullptr, 0);
    }
}